// round 4
// baseline (speedup 1.0000x reference)
#include <cuda_runtime.h>
#include <cstdint>

#define B_   8
#define S_   4096
#define D_   1024
#define R_   256
#define BS_  (B_*S_)        // 32768
#define NCH  64
#define CHUNK 64            // NCH*CHUNK == S_
#define LDT  36
#define STAGE_F (128*LDT)   // floats per stage per operand
#define NSTG 3
#define LDE  132

// ---- device scratch (no allocations allowed) ----
__device__ float g_xm[B_*D_];
__device__ float g_rnorm[BS_];
__device__ float g_fnorm[R_*D_];        // L2-normalized freqs, tf32-rounded
__device__ float g_gate[B_*R_];
__device__ float g_ret[B_*R_];
__device__ float g_sig[(size_t)BS_*R_]; // locally-scanned -> fully scanned(tf32)
__device__ float g_carry[B_*NCH*R_];

__device__ __forceinline__ uint32_t f2tf32(float v) {
    uint32_t u;
    asm("cvt.rna.tf32.f32 %0, %1;" : "=r"(u) : "f"(v));
    return u;
}

__device__ __forceinline__ void mma_tf32(float c[4], uint32_t a0, uint32_t a1,
                                         uint32_t a2, uint32_t a3,
                                         uint32_t b0, uint32_t b1) {
    asm volatile(
        "mma.sync.aligned.m16n8k8.row.col.f32.tf32.tf32.f32 "
        "{%0,%1,%2,%3}, {%4,%5,%6,%7}, {%8,%9}, {%0,%1,%2,%3};"
        : "+f"(c[0]), "+f"(c[1]), "+f"(c[2]), "+f"(c[3])
        : "r"(a0), "r"(a1), "r"(a2), "r"(a3), "r"(b0), "r"(b1));
}

__device__ __forceinline__ void cp16(uint32_t smem_dst, const void* gptr) {
    asm volatile("cp.async.cg.shared.global [%0], [%1], 16;\n"
                 :: "r"(smem_dst), "l"(gptr));
}

// ---- K0: zero xm accumulator ----
__global__ void k0_zero() {
    int i = blockIdx.x * 1024 + threadIdx.x;
    if (i < B_*D_) g_xm[i] = 0.f;
}

// ---- K1: per-row inverse norms + column sums (for mean) ----
__global__ __launch_bounds__(256) void k1_stats(const float* __restrict__ x) {
    __shared__ float sxm[8][D_];   // 32KB
    int blk  = blockIdx.x;
    int warp = threadIdx.x >> 5, lane = threadIdx.x & 31;
    float cs[32];
#pragma unroll
    for (int k = 0; k < 32; k++) cs[k] = 0.f;
    int row0 = blk * 128 + warp * 16;
    for (int rr = 0; rr < 16; rr++) {
        int row = row0 + rr;
        const float* xr = x + (size_t)row * D_;
        float ss = 0.f;
#pragma unroll
        for (int k = 0; k < 32; k++) {
            float v = xr[lane + 32*k];
            cs[k] += v;
            ss = fmaf(v, v, ss);
        }
#pragma unroll
        for (int o = 16; o > 0; o >>= 1) ss += __shfl_xor_sync(0xffffffffu, ss, o);
        if (lane == 0) g_rnorm[row] = 1.f / fmaxf(sqrtf(ss), 1e-12f);
    }
#pragma unroll
    for (int k = 0; k < 32; k++) sxm[warp][lane + 32*k] = cs[k];
    __syncthreads();
    int b = (blk * 128) / S_;
    for (int d = threadIdx.x; d < D_; d += 256) {
        float s = 0.f;
#pragma unroll
        for (int w = 0; w < 8; w++) s += sxm[w][d];
        atomicAdd(&g_xm[b*D_ + d], s);
    }
}

// ---- K2: f_norm (tf32-rounded) + gate + retention ----
__global__ __launch_bounds__(256) void k2_prep(const float* __restrict__ freq,
                                               const float* __restrict__ rbias,
                                               const float* __restrict__ rw,
                                               const float* __restrict__ gw,
                                               const float* __restrict__ gbias) {
    int r = blockIdx.x;
    int t = threadIdx.x, warp = t >> 5, lane = t & 31;
    __shared__ float red[256];

    const float* fr = freq + (size_t)r * D_;
    float fv[4]; float ss = 0.f;
#pragma unroll
    for (int i = 0; i < 4; i++) { fv[i] = fr[t + 256*i]; ss = fmaf(fv[i], fv[i], ss); }
    red[t] = ss; __syncthreads();
    if (t < 128) red[t] += red[t+128]; __syncthreads();
    if (t < 64)  red[t] += red[t+64];  __syncthreads();
    if (t < 32) {
        float v = red[t] + red[t+32];
#pragma unroll
        for (int o = 16; o > 0; o >>= 1) v += __shfl_xor_sync(0xffffffffu, v, o);
        if (t == 0) red[0] = v;
    }
    __syncthreads();
    float inv = 1.f / fmaxf(sqrtf(red[0]), 1e-12f);
#pragma unroll
    for (int i = 0; i < 4; i++)
        g_fnorm[(size_t)r*D_ + t + 256*i] = __uint_as_float(f2tf32(fv[i] * inv));

    int b = warp;
    const float* gwr = gw + (size_t)r * D_;
    const float* rwr = rw + (size_t)r * D_;
    float ag = 0.f, ar = 0.f;
    const float invS = 1.f / (float)S_;
    for (int k = lane; k < D_; k += 32) {
        float xm = g_xm[b*D_ + k] * invS;
        ag = fmaf(xm, gwr[k], ag);
        ar = fmaf(xm, rwr[k], ar);
    }
#pragma unroll
    for (int o = 16; o > 0; o >>= 1) {
        ag += __shfl_xor_sync(0xffffffffu, ag, o);
        ar += __shfl_xor_sync(0xffffffffu, ar, o);
    }
    if (lane == 0) {
        float gl = ag + gbias[r];
        float gs = 1.f / (1.f + expf(-gl));
        g_gate[b*R_ + r] = (gs >= 0.001f) ? gs : 0.f;
        float rl = ar + rbias[r];
        g_ret[b*R_ + r] = 1.f / (1.f + expf(-rl));
    }
}

// ============ pipelined tf32 GEMM compute ============
template<bool CVT_A, bool CVT_B>
__device__ __forceinline__ void gemm_compute_stage(const float* __restrict__ Asb,
                                                   const float* __restrict__ Bsb,
                                                   int wm, int wn, int grp, int tid4,
                                                   float c[4][4][4]) {
#pragma unroll
    for (int kk = 0; kk < 4; kk++) {
        int ko = kk * 8;
        uint32_t a[4][4], bf[4][2];
#pragma unroll
        for (int mt = 0; mt < 4; mt++) {
            int m0 = wm*64 + mt*16;
            if (CVT_A) {
                a[mt][0] = f2tf32(Asb[(m0+grp)*LDT   + ko + tid4]);
                a[mt][1] = f2tf32(Asb[(m0+8+grp)*LDT + ko + tid4]);
                a[mt][2] = f2tf32(Asb[(m0+grp)*LDT   + ko + tid4 + 4]);
                a[mt][3] = f2tf32(Asb[(m0+8+grp)*LDT + ko + tid4 + 4]);
            } else {
                a[mt][0] = __float_as_uint(Asb[(m0+grp)*LDT   + ko + tid4]);
                a[mt][1] = __float_as_uint(Asb[(m0+8+grp)*LDT + ko + tid4]);
                a[mt][2] = __float_as_uint(Asb[(m0+grp)*LDT   + ko + tid4 + 4]);
                a[mt][3] = __float_as_uint(Asb[(m0+8+grp)*LDT + ko + tid4 + 4]);
            }
        }
#pragma unroll
        for (int nt = 0; nt < 4; nt++) {
            int n0 = wn*32 + nt*8;
            if (CVT_B) {
                bf[nt][0] = f2tf32(Bsb[(n0+grp)*LDT + ko + tid4]);
                bf[nt][1] = f2tf32(Bsb[(n0+grp)*LDT + ko + tid4 + 4]);
            } else {
                bf[nt][0] = __float_as_uint(Bsb[(n0+grp)*LDT + ko + tid4]);
                bf[nt][1] = __float_as_uint(Bsb[(n0+grp)*LDT + ko + tid4 + 4]);
            }
        }
#pragma unroll
        for (int mt = 0; mt < 4; mt++)
#pragma unroll
            for (int nt = 0; nt < 4; nt++)
                mma_tf32(c[mt][nt], a[mt][0], a[mt][1], a[mt][2], a[mt][3],
                         bf[nt][0], bf[nt][1]);
    }
}

// ---- K3: resonance GEMM + scale + fused chunk-local scan -> g_sig, g_carry ----
__global__ __launch_bounds__(256, 2) void k3_resonance(const float* __restrict__ x) {
    extern __shared__ float smem[];
    float* As = smem;                    // NSTG stages
    float* Bs = smem + NSTG*STAGE_F;     // NSTG stages
    uint32_t as_b = (uint32_t)__cvta_generic_to_shared(As);
    uint32_t bs_b = (uint32_t)__cvta_generic_to_shared(Bs);

    int nbase = blockIdx.x * 128;
    int mbase = blockIdx.y * 128;
    int t = threadIdx.x;
    int warp = t >> 5, lane = t & 31;
    int wm = warp >> 2, wn = warp & 3;
    int grp = lane >> 2, tid4 = lane & 3;
    int lrow = t >> 3, lk = (t & 7) * 4;

    float c[4][4][4];
#pragma unroll
    for (int mt = 0; mt < 4; mt++)
#pragma unroll
        for (int nt = 0; nt < 4; nt++)
#pragma unroll
            for (int i = 0; i < 4; i++) c[mt][nt][i] = 0.f;

    const float* Ag = x + (size_t)mbase * D_;
    const float* Bg = g_fnorm + (size_t)nbase * D_;

    auto prefetch = [&](int st, int k0) {
        uint32_t ao = as_b + (uint32_t)(st*STAGE_F)*4u;
        uint32_t bo = bs_b + (uint32_t)(st*STAGE_F)*4u;
#pragma unroll
        for (int i = 0; i < 4; i++) {
            int row = lrow + i*32;
            cp16(ao + (uint32_t)(row*LDT + lk)*4u, Ag + (size_t)row*D_ + k0 + lk);
            cp16(bo + (uint32_t)(row*LDT + lk)*4u, Bg + (size_t)row*D_ + k0 + lk);
        }
        asm volatile("cp.async.commit_group;\n");
    };

    const int NK = D_ / 32;   // 32
    prefetch(0, 0);
    prefetch(1, 32);
    for (int kt = 0; kt < NK; kt++) {
        if (kt == NK-1) asm volatile("cp.async.wait_group 0;\n");
        else            asm volatile("cp.async.wait_group 1;\n");
        __syncthreads();
        if (kt + 2 < NK) prefetch((kt+2)%NSTG, (kt+2)*32);
        gemm_compute_stage<true,false>(As + (kt%NSTG)*STAGE_F, Bs + (kt%NSTG)*STAGE_F,
                                       wm, wn, grp, tid4, c);
    }

    // ---- fused epilogue: scale -> smem -> chunk-local scan -> g_sig + carries ----
    __syncthreads();            // all compute done; reuse smem
    float* Es = smem;           // 128 x LDE = 67.6KB
    int b = mbase / S_;
#pragma unroll
    for (int mt = 0; mt < 4; mt++) {
        int m0l = wm*64 + mt*16 + grp;
        float rn0 = g_rnorm[mbase + m0l], rn1 = g_rnorm[mbase + m0l + 8];
#pragma unroll
        for (int nt = 0; nt < 4; nt++) {
            int nl = wn*32 + nt*8 + tid4*2;
            float gg0 = g_gate[b*R_ + nbase + nl], gg1 = g_gate[b*R_ + nbase + nl + 1];
            Es[m0l*LDE + nl]       = c[mt][nt][0]*rn0*gg0;
            Es[m0l*LDE + nl + 1]   = c[mt][nt][1]*rn0*gg1;
            Es[(m0l+8)*LDE + nl]   = c[mt][nt][2]*rn1*gg0;
            Es[(m0l+8)*LDE + nl+1] = c[mt][nt][3]*rn1*gg1;
        }
    }
    __syncthreads();

    int ch = t >> 7;            // 0..1 (two 64-row chunks in this tile)
    int n  = t & 127;
    float ret = g_ret[b*R_ + nbase + n];
    size_t gb = ((size_t)(mbase + ch*64)) * R_ + nbase + n;
    float st = 0.f;
#pragma unroll 8
    for (int s = 0; s < CHUNK; s++) {
        st = fmaf(st, ret, Es[(ch*64 + s)*LDE + n]);
        g_sig[gb + (size_t)s*R_] = st;
    }
    int chg = (mbase % S_) / CHUNK + ch;
    g_carry[(b*NCH + chg)*R_ + nbase + n] = st;
}

// ---- K4: apply chunk prefixes; store tf32-rounded acc; emit final_state ----
__global__ __launch_bounds__(256) void k_scan2(const float* __restrict__ prev,
                                               float* __restrict__ fs_out,
                                               int write_fs) {
    int blk = blockIdx.x;
    int b = blk / NCH, ch = blk % NCH;
    int r = threadIdx.x;
    float ret = g_ret[b*R_ + r];
    float q = ret;
#pragma unroll
    for (int i = 0; i < 6; i++) q = q * q;   // ret^64
    float e = prev[b*R_ + r];
    for (int j = 0; j < ch; j++)
        e = fmaf(e, q, g_carry[(b*NCH + j)*R_ + r]);

    size_t base = ((size_t)(b*S_ + ch*CHUNK)) * R_ + r;
    float p = ret;
    float last = 0.f;
    for (int g = 0; g < CHUNK/8; g++) {
        float v[8];
#pragma unroll
        for (int j = 0; j < 8; j++) v[j] = g_sig[base + (size_t)(g*8+j)*R_];
#pragma unroll
        for (int j = 0; j < 8; j++) {
            float o = fmaf(e, p, v[j]);
            g_sig[base + (size_t)(g*8+j)*R_] = __uint_as_float(f2tf32(o));
            p *= ret;
            last = o;   // exact fp32 for final_state
        }
    }
    if (write_fs && ch == NCH-1)
        fs_out[b*R_ + r] = last;
}

// ---- K5: output GEMM: acc(tf32) @ out_w^T (cvt in B-frag load) ----
__global__ __launch_bounds__(256, 2) void k5_output(const float* __restrict__ outw,
                                                    float* __restrict__ out) {
    extern __shared__ float smem[];
    float* As = smem;
    float* Bs = smem + NSTG*STAGE_F;
    uint32_t as_b = (uint32_t)__cvta_generic_to_shared(As);
    uint32_t bs_b = (uint32_t)__cvta_generic_to_shared(Bs);

    int nbase = blockIdx.x * 128;
    int mbase = blockIdx.y * 128;
    int t = threadIdx.x;
    int warp = t >> 5, lane = t & 31;
    int wm = warp >> 2, wn = warp & 3;
    int grp = lane >> 2, tid4 = lane & 3;
    int lrow = t >> 3, lk = (t & 7) * 4;

    float c[4][4][4];
#pragma unroll
    for (int mt = 0; mt < 4; mt++)
#pragma unroll
        for (int nt = 0; nt < 4; nt++)
#pragma unroll
            for (int i = 0; i < 4; i++) c[mt][nt][i] = 0.f;

    const float* Ag = g_sig + (size_t)mbase * R_;
    const float* Bg = outw + (size_t)nbase * R_;

    auto prefetch = [&](int st, int k0) {
        uint32_t ao = as_b + (uint32_t)(st*STAGE_F)*4u;
        uint32_t bo = bs_b + (uint32_t)(st*STAGE_F)*4u;
#pragma unroll
        for (int i = 0; i < 4; i++) {
            int row = lrow + i*32;
            cp16(ao + (uint32_t)(row*LDT + lk)*4u, Ag + (size_t)row*R_ + k0 + lk);
            cp16(bo + (uint32_t)(row*LDT + lk)*4u, Bg + (size_t)row*R_ + k0 + lk);
        }
        asm volatile("cp.async.commit_group;\n");
    };

    const int NK = R_ / 32;   // 8
    prefetch(0, 0);
    prefetch(1, 32);
    for (int kt = 0; kt < NK; kt++) {
        if (kt == NK-1) asm volatile("cp.async.wait_group 0;\n");
        else            asm volatile("cp.async.wait_group 1;\n");
        __syncthreads();
        if (kt + 2 < NK) prefetch((kt+2)%NSTG, (kt+2)*32);
        gemm_compute_stage<false,true>(As + (kt%NSTG)*STAGE_F, Bs + (kt%NSTG)*STAGE_F,
                                       wm, wn, grp, tid4, c);
    }

#pragma unroll
    for (int mt = 0; mt < 4; mt++) {
        int m0 = mbase + wm*64 + mt*16 + grp;
#pragma unroll
        for (int nt = 0; nt < 4; nt++) {
            int n = nbase + wn*32 + nt*8 + tid4*2;
            float2 v0 = make_float2(c[mt][nt][0], c[mt][nt][1]);
            float2 v1 = make_float2(c[mt][nt][2], c[mt][nt][3]);
            *(float2*)&out[(size_t)m0*D_ + n]     = v0;
            *(float2*)&out[(size_t)(m0+8)*D_ + n] = v1;
        }
    }
}

extern "C" void kernel_launch(void* const* d_in, const int* in_sizes, int n_in,
                              void* d_out, int out_size) {
    const float* x     = (const float*)d_in[0];
    const float* prev  = (const float*)d_in[1];
    const float* freq  = (const float*)d_in[2];
    const float* rbias = (const float*)d_in[3];
    const float* rw    = (const float*)d_in[4];
    const float* gw    = (const float*)d_in[5];
    const float* gbias = (const float*)d_in[6];
    const float* outw  = (const float*)d_in[7];
    float* out = (float*)d_out;

    const int SMEM_GEMM = NSTG * 2 * STAGE_F * 4;   // 110592 bytes
    cudaFuncSetAttribute(k3_resonance, cudaFuncAttributeMaxDynamicSharedMemorySize, SMEM_GEMM);
    cudaFuncSetAttribute(k5_output,    cudaFuncAttributeMaxDynamicSharedMemorySize, SMEM_GEMM);

    const int out_elems = B_*S_*D_;
    int write_fs = (out_size >= out_elems + B_*R_) ? 1 : 0;
    float* fs = out + out_elems;

    k0_zero<<<8, 1024>>>();
    k1_stats<<<256, 256>>>(x);
    k2_prep<<<256, 256>>>(freq, rbias, rw, gw, gbias);
    k3_resonance<<<dim3(2, 256), 256, SMEM_GEMM>>>(x);
    k_scan2<<<B_*NCH, 256>>>(prev, fs, write_fs);
    k5_output<<<dim3(8, 256), 256, SMEM_GEMM>>>(outw, out);
}